// round 5
// baseline (speedup 1.0000x reference)
#include <cuda_runtime.h>

// ---------------------------------------------------------------------------
// SSIM 3D, 11-tap separable Gaussian, VALID. Round 5:
// Kernel 1: fused W-conv + H-conv (stream h, 23-row smem product ring,
//           register-prefetched img rows) -> s2 [f][n][oh][d][w pad 184]
// Kernel 2: D-conv over 5 fields + SSIM + deterministic reduce.
// Total DRAM traffic ~643 MB (vs 1.33 GB in R4).
// ---------------------------------------------------------------------------

__device__ constexpr float CG[11] = {
    0.0010283817f, 0.0075987700f, 0.0360007700f, 0.1093607000f,
    0.2130055500f, 0.2660117200f,
    0.2130055500f, 0.1093607000f, 0.0360007700f, 0.0075987700f,
    0.0010283817f
};

static const size_t FS3 = (size_t)2 * 182 * 192 * 184;   // 12,859,392 per field
__device__ float d_s2[5 * FS3];

__device__ unsigned d_minbits;
__device__ unsigned d_maxbits;
__device__ float    d_c1c2[2];
__device__ float    d_bsum[4368];

// ---------------------------------------------------------------------------

__global__ void init_kernel() {
    d_minbits = 0xFFFFFFFFu;
    d_maxbits = 0u;
}

__device__ __forceinline__ float mono2f(unsigned u) {
    return (u & 0x80000000u) ? __uint_as_float(u ^ 0x80000000u)
                             : __uint_as_float(~u);
}
__device__ __forceinline__ void mono_acc(float f, unsigned& mn, unsigned& mx) {
    unsigned u = __float_as_uint(f);
    u = (u & 0x80000000u) ? ~u : (u | 0x80000000u);
    mn = min(mn, u);
    mx = max(mx, u);
}

__global__ void const_kernel() {
    float mx = mono2f(d_maxbits);
    float mn = mono2f(d_minbits);
    float max_val = (mx > 128.0f) ? 255.0f : 1.0f;
    float min_val = (mn < -0.5f) ? -1.0f : 0.0f;
    float L = max_val - min_val;
    float c1 = 0.01f * L, c2 = 0.03f * L;
    d_c1c2[0] = c1 * c1;
    d_c1c2[1] = c2 * c2;
}

// ---------------------------------------------------------------------------
// Kernel 1: fused W+H conv. Block = (n, d, w-half). 256 threads.
// Streams h in 15 chunks of <=13 rows; register-prefetch next chunk;
// 5-field x 23-row x 92-col smem ring; gathers H conv from the ring.
// ---------------------------------------------------------------------------
__global__ void __launch_bounds__(256) passWH_kernel(
    const float* __restrict__ img1, const float* __restrict__ img2) {
    __shared__ float simg[2][2][13][104];     // [buf][img][row][w]
    __shared__ float sprod[5][23][92];        // ring over h (slot = h % 23)
    __shared__ unsigned smin[8], smax[8];

    const int tid  = threadIdx.x;
    const int half = blockIdx.x & 1;
    const int nd   = blockIdx.x >> 1;          // n*192 + d
    const int n    = nd / 192;
    const int d    = nd % 192;
    const int walign = half ? 88 : 0;          // f4-aligned input w base
    const int w0     = half ? 91 : 0;          // output w base (91 outputs)
    const int woff   = w0 - walign;            // 0 or 3

    const size_t ibase = (size_t)nd * 36864 + (size_t)walign;   // + h*192

    unsigned lmin = 0xFFFFFFFFu, lmax = 0u;
    float4 st[3];

    // stage loader for chunk cc: 676 float4 items (2 imgs x nrow rows x 26 f4)
    auto stage_load = [&](int cc) {
        int hlo = cc * 13;
        int nrow = (192 - hlo < 13) ? (192 - hlo) : 13;
        #pragma unroll
        for (int q = 0; q < 3; q++) {
            int it = tid + q * 256;
            st[q] = make_float4(0.f, 0.f, 0.f, 0.f);
            if (it < 676) {
                int im  = it / 338;
                int rem = it % 338;
                int rr  = rem / 26;
                int c4  = rem % 26;
                if (rr < nrow) {
                    const float* p = im ? img2 : img1;
                    st[q] = __ldg((const float4*)(p + ibase + (size_t)(hlo + rr) * 192) + c4);
                    if (im == 0) {
                        mono_acc(st[q].x, lmin, lmax);
                        mono_acc(st[q].y, lmin, lmax);
                        mono_acc(st[q].z, lmin, lmax);
                        mono_acc(st[q].w, lmin, lmax);
                    }
                }
            }
        }
    };

    stage_load(0);

    for (int c = 0; c < 15; c++) {
        const int hlo = c * 13;
        const int nrow = (192 - hlo < 13) ? (192 - hlo) : 13;
        const int buf = c & 1;

        // commit staged regs -> simg[buf]
        #pragma unroll
        for (int q = 0; q < 3; q++) {
            int it = tid + q * 256;
            if (it < 676) {
                int im  = it / 338;
                int rem = it % 338;
                int rr  = rem / 26;
                int c4  = rem % 26;
                ((float4*)&simg[buf][im][rr][0])[c4] = st[q];
            }
        }
        __syncthreads();   // simg ready; also separates prior gather from ring refill

        if (c < 14) stage_load(c + 1);   // prefetch: loads in flight during compute

        // W-conv + products into the ring
        for (int it = tid; it < nrow * 91; it += 256) {
            int rr = it / 91;
            int j  = it % 91;
            float a0 = 0.f, a1 = 0.f, a2 = 0.f, a3 = 0.f, a4 = 0.f;
            #pragma unroll
            for (int k = 0; k < 11; k++) {
                float x = simg[buf][0][rr][woff + j + k];
                float y = simg[buf][1][rr][woff + j + k];
                float tx = CG[k] * x, ty = CG[k] * y;
                a0 += tx;
                a1 += ty;
                a2 += tx * x;
                a3 += ty * y;
                a4 += tx * y;
            }
            int slot = (hlo + rr) % 23;
            sprod[0][slot][j] = a0;
            sprod[1][slot][j] = a1;
            sprod[2][slot][j] = a2;
            sprod[3][slot][j] = a3;
            sprod[4][slot][j] = a4;
        }
        __syncthreads();

        // H-conv gather from ring -> global s2
        int ohlo = (hlo - 10 > 0) ? (hlo - 10) : 0;
        int ohhi = hlo + nrow - 11;
        int nout = ohhi - ohlo + 1;        // 3, 13, ..., 13, 10
        int per_f = nout * 91;
        for (int it = tid; it < 5 * per_f; it += 256) {
            int f   = it / per_f;
            int rem = it % per_f;
            int r   = rem / 91;
            int j   = rem % 91;
            int oh  = ohlo + r;
            int s0  = oh % 23;
            float a = 0.f;
            #pragma unroll
            for (int k = 0; k < 11; k++) {
                int sl = s0 + k;
                if (sl >= 23) sl -= 23;
                a += CG[k] * sprod[f][sl][j];
            }
            d_s2[(size_t)f * FS3 + ((size_t)(n * 182 + oh) * 192 + d) * 184
                 + (size_t)(w0 + j)] = a;
        }
        // loop-top __syncthreads protects the ring for the next refill
    }

    // min/max reduce -> atomics
    #pragma unroll
    for (int off = 16; off; off >>= 1) {
        lmin = min(lmin, __shfl_down_sync(0xFFFFFFFFu, lmin, off));
        lmax = max(lmax, __shfl_down_sync(0xFFFFFFFFu, lmax, off));
    }
    int wid = tid >> 5, lane = tid & 31;
    if (lane == 0) { smin[wid] = lmin; smax[wid] = lmax; }
    __syncthreads();
    if (tid == 0) {
        #pragma unroll
        for (int i = 1; i < 8; i++) {
            lmin = min(lmin, smin[i]);
            lmax = max(lmax, smax[i]);
        }
        atomicMin(&d_minbits, lmin);
        atomicMax(&d_maxbits, lmax);
    }
}

// ---------------------------------------------------------------------------
// Kernel 2: D conv (5 fields) + SSIM + block sum. Block = (n, oh, w-tile 16).
// smem 5 x 192 x 16 (61 KB). 14 strips x 13 outputs, 5x11 ring, SSIM inline.
// ---------------------------------------------------------------------------
__global__ void __launch_bounds__(256) passD_kernel() {
    __shared__ float sm[5][192 * 16];
    __shared__ float sred[256];

    int wt   = blockIdx.x % 12;
    int rest = blockIdx.x / 12;
    int oh = rest % 182;
    int n  = rest / 182;

    size_t pb = (size_t)(n * 182 + oh) * (192 * 184) + (size_t)wt * 16;

    for (int i = threadIdx.x; i < 5 * 192 * 4; i += 256) {   // 3840 float4
        int c  = i & 3;
        int dd = (i >> 2) % 192;
        int f  = i / 768;
        float4 v = __ldg((const float4*)(d_s2 + (size_t)f * FS3 + pb + (size_t)dd * 184) + c);
        ((float4*)(&sm[f][0]))[dd * 4 + c] = v;
    }
    __syncthreads();

    const float C1 = d_c1c2[0];
    const float C2 = d_c1c2[1];
    float lsum = 0.f;
    int tid = threadIdx.x;

    if (tid < 224) {
        int w = tid & 15;
        int s = tid >> 4;              // strip 0..13
        int ow = wt * 16 + w;
        if (ow < 182) {
            int d0 = s * 13;
            float acc[5][11];
            #pragma unroll
            for (int j = 0; j < 23; j++) {
                const int J = j % 11;
                float v0 = sm[0][(d0 + j) * 16 + w];
                float v1 = sm[1][(d0 + j) * 16 + w];
                float v2 = sm[2][(d0 + j) * 16 + w];
                float v3 = sm[3][(d0 + j) * 16 + w];
                float v4 = sm[4][(d0 + j) * 16 + w];
                acc[0][J] = CG[0] * v0;
                acc[1][J] = CG[0] * v1;
                acc[2][J] = CG[0] * v2;
                acc[3][J] = CG[0] * v3;
                acc[4][J] = CG[0] * v4;
                #pragma unroll
                for (int k = 1; k < 11; k++) {
                    const int e = (J + 11 - k) % 11;
                    acc[0][e] += CG[k] * v0;
                    acc[1][e] += CG[k] * v1;
                    acc[2][e] += CG[k] * v2;
                    acc[3][e] += CG[k] * v3;
                    acc[4][e] += CG[k] * v4;
                }
                if (j >= 10) {
                    const int e = (J + 1) % 11;
                    float mu1 = acc[0][e], mu2 = acc[1][e];
                    float m11 = mu1 * mu1, m22 = mu2 * mu2, m12 = mu1 * mu2;
                    float s11 = acc[2][e] - m11;
                    float s22 = acc[3][e] - m22;
                    float s12 = acc[4][e] - m12;
                    float va = 2.f * s12 + C2;
                    float vb = s11 + s22 + C2;
                    float num = (2.f * m12 + C1) * va;
                    float den = (m11 + m22 + C1) * vb;
                    lsum += __fdividef(num, den);
                }
            }
        }
    }

    sred[tid] = lsum;
    __syncthreads();
    #pragma unroll
    for (int off = 128; off; off >>= 1) {
        if (tid < off) sred[tid] += sred[tid + off];
        __syncthreads();
    }
    if (tid == 0) d_bsum[blockIdx.x] = sred[0];
}

// Deterministic final reduction over 4368 block sums.
__global__ void final_kernel(float* __restrict__ out) {
    __shared__ double sd[256];
    double s = 0.0;
    for (int i = threadIdx.x; i < 4368; i += 256) s += (double)d_bsum[i];
    sd[threadIdx.x] = s;
    __syncthreads();
    #pragma unroll
    for (int off = 128; off; off >>= 1) {
        if (threadIdx.x < off) sd[threadIdx.x] += sd[threadIdx.x + off];
        __syncthreads();
    }
    if (threadIdx.x == 0)
        out[0] = (float)(sd[0] / 12057136.0);   // 2 * 182^3
}

// ---------------------------------------------------------------------------

extern "C" void kernel_launch(void* const* d_in, const int* in_sizes, int n_in,
                              void* d_out, int out_size) {
    const float* img1 = (const float*)d_in[0];
    const float* img2 = (const float*)d_in[1];
    float* out = (float*)d_out;

    init_kernel<<<1, 1>>>();
    passWH_kernel<<<768, 256>>>(img1, img2);   // 2*192 (n,d) x 2 w-halves
    const_kernel<<<1, 1>>>();
    passD_kernel<<<4368, 256>>>();             // 2*182 (n,oh) x 12 w-tiles
    final_kernel<<<1, 256>>>(out);
}

// round 6
// speedup vs baseline: 2.4563x; 2.4563x over previous
#include <cuda_runtime.h>
#include <cuda_fp16.h>

// ---------------------------------------------------------------------------
// SSIM 3D, 11-tap separable Gaussian, VALID. Round 6:
// R1's proven 3-pass strip structure + fp16 scratch (halves DRAM bytes)
// + 26-long pass2 strips (amp 1.77x -> 1.38x) + minmax fused into pass1.
// ---------------------------------------------------------------------------

__device__ constexpr float CG[11] = {
    0.0010283817f, 0.0075987700f, 0.0360007700f, 0.1093607000f,
    0.2130055500f, 0.2660117200f,
    0.2130055500f, 0.1093607000f, 0.0360007700f, 0.0075987700f,
    0.0010283817f
};

// s1: [f][n][d][h(192)][w(184 pad, 182 valid)]   half
// s2: [f][n][d][oh(182)][w(184 pad, 182 valid)]  half
static const size_t FS1 = (size_t)2 * 192 * 192 * 184;   // 13,565,952 halves
static const size_t FS2 = (size_t)2 * 192 * 182 * 184;   // 12,859,392 halves
__device__ __half d_s1[5 * FS1];
__device__ __half d_s2[5 * FS2];

__device__ unsigned d_minbits;
__device__ unsigned d_maxbits;
__device__ float    d_c1c2[2];
__device__ float    d_bsum[3623];

// ---------------------------------------------------------------------------

__global__ void init_kernel() {
    d_minbits = 0xFFFFFFFFu;
    d_maxbits = 0u;
}

__device__ __forceinline__ float mono2f(unsigned u) {
    return (u & 0x80000000u) ? __uint_as_float(u ^ 0x80000000u)
                             : __uint_as_float(~u);
}
__device__ __forceinline__ void mono_acc(float f, unsigned& mn, unsigned& mx) {
    unsigned u = __float_as_uint(f);
    u = (u & 0x80000000u) ? ~u : (u | 0x80000000u);
    mn = min(mn, u);
    mx = max(mx, u);
}

__global__ void const_kernel() {
    float mx = mono2f(d_maxbits);
    float mn = mono2f(d_minbits);
    float max_val = (mx > 128.0f) ? 255.0f : 1.0f;
    float min_val = (mn < -0.5f) ? -1.0f : 0.0f;
    float L = max_val - min_val;
    float c1 = 0.01f * L, c2 = 0.03f * L;
    d_c1c2[0] = c1 * c1;
    d_c1c2[1] = c2 * c2;
}

// ---------------------------------------------------------------------------
// Pass 1: W conv + 5 products + img1 min/max. Block = (n,d, 8 h-rows).
// 192 threads; float4 smem fill; half stores (364B contiguous per row-field).
// ---------------------------------------------------------------------------
__global__ void __launch_bounds__(192) pass1_kernel(
    const float* __restrict__ img1, const float* __restrict__ img2) {
    __shared__ float sx[8 * 192];
    __shared__ float sy[8 * 192];

    int hg = blockIdx.x % 24;
    int nd = blockIdx.x / 24;          // n*192 + d
    int h0 = hg * 8;
    size_t base = ((size_t)nd * 192 + h0) * 192;
    int tid = threadIdx.x;

    unsigned lmin = 0xFFFFFFFFu, lmax = 0u;
    const float4* p1 = (const float4*)(img1 + base);
    const float4* p2 = (const float4*)(img2 + base);
    #pragma unroll
    for (int j = 0; j < 2; j++) {
        int idx = tid + j * 192;       // 0..383 float4
        float4 a = __ldg(&p1[idx]);
        float4 b = __ldg(&p2[idx]);
        ((float4*)sx)[idx] = a;
        ((float4*)sy)[idx] = b;
        mono_acc(a.x, lmin, lmax); mono_acc(a.y, lmin, lmax);
        mono_acc(a.z, lmin, lmax); mono_acc(a.w, lmin, lmax);
    }
    __syncthreads();

    if (tid < 182) {
        size_t ob = ((size_t)nd * 192 + h0) * 184 + tid;
        #pragma unroll
        for (int r = 0; r < 8; r++) {
            float a0 = 0.f, a1 = 0.f, a2 = 0.f, a3 = 0.f, a4 = 0.f;
            #pragma unroll
            for (int k = 0; k < 11; k++) {
                float g = CG[k];
                float x = sx[r * 192 + tid + k];
                float y = sy[r * 192 + tid + k];
                float tx = g * x, ty = g * y;
                a0 += tx;
                a1 += ty;
                a2 += tx * x;
                a3 += ty * y;
                a4 += tx * y;
            }
            size_t o = ob + (size_t)r * 184;
            d_s1[o]           = __float2half_rn(a0);
            d_s1[FS1 + o]     = __float2half_rn(a1);
            d_s1[2 * FS1 + o] = __float2half_rn(a2);
            d_s1[3 * FS1 + o] = __float2half_rn(a3);
            d_s1[4 * FS1 + o] = __float2half_rn(a4);
        }
    }

    // min/max block reduce -> atomics
    #pragma unroll
    for (int off = 16; off; off >>= 1) {
        lmin = min(lmin, __shfl_down_sync(0xFFFFFFFFu, lmin, off));
        lmax = max(lmax, __shfl_down_sync(0xFFFFFFFFu, lmax, off));
    }
    __shared__ unsigned smin[6], smax[6];
    int wid = tid >> 5, lane = tid & 31;
    if (lane == 0) { smin[wid] = lmin; smax[wid] = lmax; }
    __syncthreads();
    if (tid == 0) {
        #pragma unroll
        for (int i = 1; i < 6; i++) {
            lmin = min(lmin, smin[i]);
            lmax = max(lmax, smax[i]);
        }
        atomicMin(&d_minbits, lmin);
        atomicMax(&d_maxbits, lmax);
    }
}

// ---------------------------------------------------------------------------
// Pass 2: H conv, strips of 26 (182 = 7*26). Thread = (f, n, d, strip, ow).
// 36 loads -> 26 outputs (amp 1.38). Fully coalesced (thread ~ ow).
// ---------------------------------------------------------------------------
__global__ void __launch_bounds__(256) pass2_kernel() {
    const size_t TOT = (size_t)5 * 2 * 192 * 7 * 182;    // 2,446,080
    size_t idx = (size_t)blockIdx.x * 256 + threadIdx.x;
    if (idx >= TOT) return;
    int ow = (int)(idx % 182); size_t t = idx / 182;
    int strip = (int)(t % 7);
    int plane = (int)(t / 7);            // f*384 + nd
    int f  = plane / 384;
    int nd = plane % 384;
    int h0 = strip * 26;

    const __half* __restrict__ src = d_s1 + (size_t)f * FS1 + (size_t)nd * (192 * 184) + ow;
    __half* __restrict__ dst = d_s2 + (size_t)f * FS2 + (size_t)nd * (182 * 184) + ow;

    float acc[26];
    #pragma unroll
    for (int o = 0; o < 26; o++) acc[o] = 0.f;

    #pragma unroll
    for (int j = 0; j < 36; j++) {
        float v = __half2float(__ldg(&src[(size_t)(h0 + j) * 184]));
        #pragma unroll
        for (int o = 0; o < 26; o++) {
            int k = j - o;
            if (k >= 0 && k < 11) acc[o] += CG[k] * v;
        }
    }
    #pragma unroll
    for (int o = 0; o < 26; o++)
        dst[(size_t)(h0 + o) * 184] = __float2half_rn(acc[o]);
}

// ---------------------------------------------------------------------------
// Pass 3: D conv (5 fields) + SSIM + block sum. Thread = (n, strip, oh, ow).
// Strips of 13 (182 = 14*13), 23 loads x 5 fields, 65 accumulators.
// ---------------------------------------------------------------------------
__global__ void __launch_bounds__(256) pass3_kernel() {
    const size_t TOT = (size_t)2 * 14 * 182 * 182;   // 927,472
    size_t idx = (size_t)blockIdx.x * 256 + threadIdx.x;
    float lsum = 0.f;
    if (idx < TOT) {
        int ow = (int)(idx % 182); size_t t = idx / 182;
        int oh = (int)(t % 182); t /= 182;
        int strip = (int)(t % 14);
        int n = (int)(t / 14);
        int d0 = strip * 13;
        const float C1 = d_c1c2[0];
        const float C2 = d_c1c2[1];

        float a0[13], a1[13], a2[13], a3[13], a4[13];
        #pragma unroll
        for (int o = 0; o < 13; o++) {
            a0[o] = 0.f; a1[o] = 0.f; a2[o] = 0.f; a3[o] = 0.f; a4[o] = 0.f;
        }
        // s2 offset: ((n*192 + d)*182 + oh)*184 + ow ; d-stride = 182*184 = 33488
        size_t pbase = ((size_t)(n * 192 + d0) * 182 + oh) * 184 + ow;
        #pragma unroll
        for (int j = 0; j < 23; j++) {
            size_t p = pbase + (size_t)j * 33488;
            float m1  = __half2float(__ldg(&d_s2[p]));
            float m2  = __half2float(__ldg(&d_s2[p + FS2]));
            float e11 = __half2float(__ldg(&d_s2[p + 2 * FS2]));
            float e22 = __half2float(__ldg(&d_s2[p + 3 * FS2]));
            float e12 = __half2float(__ldg(&d_s2[p + 4 * FS2]));
            #pragma unroll
            for (int o = 0; o < 13; o++) {
                int k = j - o;
                if (k >= 0 && k < 11) {
                    float g = CG[k];
                    a0[o] += g * m1;
                    a1[o] += g * m2;
                    a2[o] += g * e11;
                    a3[o] += g * e22;
                    a4[o] += g * e12;
                }
            }
        }
        #pragma unroll
        for (int o = 0; o < 13; o++) {
            float mu1 = a0[o], mu2 = a1[o];
            float m11 = mu1 * mu1, m22 = mu2 * mu2, m12 = mu1 * mu2;
            float s11 = a2[o] - m11;
            float s22 = a3[o] - m22;
            float s12 = a4[o] - m12;
            float v1 = 2.f * s12 + C2;
            float v2 = s11 + s22 + C2;
            float num = (2.f * m12 + C1) * v1;
            float den = (m11 + m22 + C1) * v2;
            lsum += __fdividef(num, den);
        }
    }
    __shared__ float sred[256];
    sred[threadIdx.x] = lsum;
    __syncthreads();
    #pragma unroll
    for (int off = 128; off; off >>= 1) {
        if (threadIdx.x < off) sred[threadIdx.x] += sred[threadIdx.x + off];
        __syncthreads();
    }
    if (threadIdx.x == 0) d_bsum[blockIdx.x] = sred[0];
}

// Deterministic final reduction over 3623 block sums.
__global__ void final_kernel(float* __restrict__ out) {
    __shared__ double sd[256];
    double s = 0.0;
    for (int i = threadIdx.x; i < 3623; i += 256) s += (double)d_bsum[i];
    sd[threadIdx.x] = s;
    __syncthreads();
    #pragma unroll
    for (int off = 128; off; off >>= 1) {
        if (threadIdx.x < off) sd[threadIdx.x] += sd[threadIdx.x + off];
        __syncthreads();
    }
    if (threadIdx.x == 0)
        out[0] = (float)(sd[0] / 12057136.0);   // 2 * 182^3
}

// ---------------------------------------------------------------------------

extern "C" void kernel_launch(void* const* d_in, const int* in_sizes, int n_in,
                              void* d_out, int out_size) {
    const float* img1 = (const float*)d_in[0];
    const float* img2 = (const float*)d_in[1];
    float* out = (float*)d_out;

    init_kernel<<<1, 1>>>();
    pass1_kernel<<<9216, 192>>>(img1, img2);   // 2*192*192 rows / 8
    const_kernel<<<1, 1>>>();
    pass2_kernel<<<9555, 256>>>();             // 5*2*192*7*182 threads
    pass3_kernel<<<3623, 256>>>();             // 2*14*182*182 threads
    final_kernel<<<1, 256>>>(out);
}

// round 7
// speedup vs baseline: 2.5147x; 1.0238x over previous
#include <cuda_runtime.h>
#include <cuda_fp16.h>

// ---------------------------------------------------------------------------
// SSIM 3D, 11-tap separable Gaussian, VALID. Round 7:
// R6 + half2 pass2 (2 ow/thread), L2 temporal ordering (pass2 reads s1
// nd-descending / field-fastest so pass1's L2 tail hits, and its own write
// tail matches pass3's first reads), half2 stores in pass1.
// ---------------------------------------------------------------------------

__device__ constexpr float CG[11] = {
    0.0010283817f, 0.0075987700f, 0.0360007700f, 0.1093607000f,
    0.2130055500f, 0.2660117200f,
    0.2130055500f, 0.1093607000f, 0.0360007700f, 0.0075987700f,
    0.0010283817f
};

// s1: [f][n][d][h(192)][w(184 pad, 182 valid)]   half
// s2: [f][n][d][oh(182)][w(184 pad, 182 valid)]  half
static const size_t FS1 = (size_t)2 * 192 * 192 * 184;   // 13,565,952 halves
static const size_t FS2 = (size_t)2 * 192 * 182 * 184;   // 12,859,392 halves
__device__ __half d_s1[5 * FS1];
__device__ __half d_s2[5 * FS2];

__device__ unsigned d_minbits;
__device__ unsigned d_maxbits;
__device__ float    d_c1c2[2];
__device__ float    d_bsum[3623];

// ---------------------------------------------------------------------------

__global__ void init_kernel() {
    d_minbits = 0xFFFFFFFFu;
    d_maxbits = 0u;
}

__device__ __forceinline__ float mono2f(unsigned u) {
    return (u & 0x80000000u) ? __uint_as_float(u ^ 0x80000000u)
                             : __uint_as_float(~u);
}
__device__ __forceinline__ void mono_acc(float f, unsigned& mn, unsigned& mx) {
    unsigned u = __float_as_uint(f);
    u = (u & 0x80000000u) ? ~u : (u | 0x80000000u);
    mn = min(mn, u);
    mx = max(mx, u);
}

__global__ void const_kernel() {
    float mx = mono2f(d_maxbits);
    float mn = mono2f(d_minbits);
    float max_val = (mx > 128.0f) ? 255.0f : 1.0f;
    float min_val = (mn < -0.5f) ? -1.0f : 0.0f;
    float L = max_val - min_val;
    float c1 = 0.01f * L, c2 = 0.03f * L;
    d_c1c2[0] = c1 * c1;
    d_c1c2[1] = c2 * c2;
}

// ---------------------------------------------------------------------------
// Pass 1: W conv + 5 products + img1 min/max. Block = (n,d, 8 h-rows).
// 192 threads; float4 smem fill; item loop over (row, ow-pair) -> half2 store.
// ---------------------------------------------------------------------------
__global__ void __launch_bounds__(192) pass1_kernel(
    const float* __restrict__ img1, const float* __restrict__ img2) {
    __shared__ float sx[8 * 192];
    __shared__ float sy[8 * 192];

    int hg = blockIdx.x % 24;
    int nd = blockIdx.x / 24;          // n*192 + d
    int h0 = hg * 8;
    size_t base = ((size_t)nd * 192 + h0) * 192;
    int tid = threadIdx.x;

    unsigned lmin = 0xFFFFFFFFu, lmax = 0u;
    const float4* p1 = (const float4*)(img1 + base);
    const float4* p2 = (const float4*)(img2 + base);
    #pragma unroll
    for (int j = 0; j < 2; j++) {
        int idx = tid + j * 192;       // 0..383 float4
        float4 a = __ldg(&p1[idx]);
        float4 b = __ldg(&p2[idx]);
        ((float4*)sx)[idx] = a;
        ((float4*)sy)[idx] = b;
        mono_acc(a.x, lmin, lmax); mono_acc(a.y, lmin, lmax);
        mono_acc(a.z, lmin, lmax); mono_acc(a.w, lmin, lmax);
    }
    __syncthreads();

    size_t ob = ((size_t)nd * 192 + h0) * 184;
    for (int i = tid; i < 8 * 91; i += 192) {
        int r = i / 91;
        int p = (i % 91) * 2;          // ow pair: p, p+1
        float a0l = 0.f, a1l = 0.f, a2l = 0.f, a3l = 0.f, a4l = 0.f;
        float a0h = 0.f, a1h = 0.f, a2h = 0.f, a3h = 0.f, a4h = 0.f;
        #pragma unroll
        for (int k = 0; k < 11; k++) {
            float g = CG[k];
            float x = sx[r * 192 + p + k];
            float y = sy[r * 192 + p + k];
            float tx = g * x, ty = g * y;
            a0l += tx; a1l += ty; a2l += tx * x; a3l += ty * y; a4l += tx * y;
            float x2 = sx[r * 192 + p + 1 + k];
            float y2 = sy[r * 192 + p + 1 + k];
            float tx2 = g * x2, ty2 = g * y2;
            a0h += tx2; a1h += ty2; a2h += tx2 * x2; a3h += ty2 * y2; a4h += tx2 * y2;
        }
        size_t o = ob + (size_t)r * 184 + p;
        *(__half2*)&d_s1[o]           = __floats2half2_rn(a0l, a0h);
        *(__half2*)&d_s1[FS1 + o]     = __floats2half2_rn(a1l, a1h);
        *(__half2*)&d_s1[2 * FS1 + o] = __floats2half2_rn(a2l, a2h);
        *(__half2*)&d_s1[3 * FS1 + o] = __floats2half2_rn(a3l, a3h);
        *(__half2*)&d_s1[4 * FS1 + o] = __floats2half2_rn(a4l, a4h);
    }

    // min/max block reduce -> atomics
    #pragma unroll
    for (int off = 16; off; off >>= 1) {
        lmin = min(lmin, __shfl_down_sync(0xFFFFFFFFu, lmin, off));
        lmax = max(lmax, __shfl_down_sync(0xFFFFFFFFu, lmax, off));
    }
    __shared__ unsigned smin[6], smax[6];
    int wid = tid >> 5, lane = tid & 31;
    if (lane == 0) { smin[wid] = lmin; smax[wid] = lmax; }
    __syncthreads();
    if (tid == 0) {
        #pragma unroll
        for (int i = 1; i < 6; i++) {
            lmin = min(lmin, smin[i]);
            lmax = max(lmax, smax[i]);
        }
        atomicMin(&d_minbits, lmin);
        atomicMax(&d_maxbits, lmax);
    }
}

// ---------------------------------------------------------------------------
// Pass 2: H conv, half2 (2 ow/thread), strips of 26 (182 = 7*26).
// Thread = (ndr desc, f, strip, owp). 36 half2 loads -> 26 half2 outputs.
// nd descending => reads hit pass1's L2-resident tail; writes end at low nd
// which pass3 reads first.
// ---------------------------------------------------------------------------
__global__ void __launch_bounds__(256) pass2_kernel() {
    const size_t TOT = (size_t)5 * 2 * 192 * 7 * 91;     // 1,223,040
    size_t idx = (size_t)blockIdx.x * 256 + threadIdx.x;
    if (idx >= TOT) return;
    int owp = (int)(idx % 91); size_t t = idx / 91;
    int strip = (int)(t % 7); t /= 7;
    int f   = (int)(t % 5);
    int nd  = 383 - (int)(t / 5);        // descending
    int h0 = strip * 26;
    int ow = owp * 2;

    const __half* __restrict__ src = d_s1 + (size_t)f * FS1 + (size_t)nd * (192 * 184) + ow;
    __half* __restrict__ dst = d_s2 + (size_t)f * FS2 + (size_t)nd * (182 * 184) + ow;

    float accl[26], acch[26];
    #pragma unroll
    for (int o = 0; o < 26; o++) { accl[o] = 0.f; acch[o] = 0.f; }

    #pragma unroll
    for (int j = 0; j < 36; j++) {
        __half2 h = __ldg((const __half2*)&src[(size_t)(h0 + j) * 184]);
        float vl = __low2float(h), vh = __high2float(h);
        #pragma unroll
        for (int o = 0; o < 26; o++) {
            int k = j - o;
            if (k >= 0 && k < 11) {
                accl[o] += CG[k] * vl;
                acch[o] += CG[k] * vh;
            }
        }
    }
    #pragma unroll
    for (int o = 0; o < 26; o++)
        *(__half2*)&dst[(size_t)(h0 + o) * 184] = __floats2half2_rn(accl[o], acch[o]);
}

// ---------------------------------------------------------------------------
// Pass 3: D conv (5 fields) + SSIM + block sum. Thread = (n, strip, oh, ow).
// Strips of 13 (182 = 14*13), 23 loads x 5 fields, 65 accumulators.
// ---------------------------------------------------------------------------
__global__ void __launch_bounds__(256) pass3_kernel() {
    const size_t TOT = (size_t)2 * 14 * 182 * 182;   // 927,472
    size_t idx = (size_t)blockIdx.x * 256 + threadIdx.x;
    float lsum = 0.f;
    if (idx < TOT) {
        int ow = (int)(idx % 182); size_t t = idx / 182;
        int oh = (int)(t % 182); t /= 182;
        int strip = (int)(t % 14);
        int n = (int)(t / 14);
        int d0 = strip * 13;
        const float C1 = d_c1c2[0];
        const float C2 = d_c1c2[1];

        float a0[13], a1[13], a2[13], a3[13], a4[13];
        #pragma unroll
        for (int o = 0; o < 13; o++) {
            a0[o] = 0.f; a1[o] = 0.f; a2[o] = 0.f; a3[o] = 0.f; a4[o] = 0.f;
        }
        // s2 offset: ((n*192 + d)*182 + oh)*184 + ow ; d-stride = 182*184 = 33488
        size_t pbase = ((size_t)(n * 192 + d0) * 182 + oh) * 184 + ow;
        #pragma unroll
        for (int j = 0; j < 23; j++) {
            size_t p = pbase + (size_t)j * 33488;
            float m1  = __half2float(__ldg(&d_s2[p]));
            float m2  = __half2float(__ldg(&d_s2[p + FS2]));
            float e11 = __half2float(__ldg(&d_s2[p + 2 * FS2]));
            float e22 = __half2float(__ldg(&d_s2[p + 3 * FS2]));
            float e12 = __half2float(__ldg(&d_s2[p + 4 * FS2]));
            #pragma unroll
            for (int o = 0; o < 13; o++) {
                int k = j - o;
                if (k >= 0 && k < 11) {
                    float g = CG[k];
                    a0[o] += g * m1;
                    a1[o] += g * m2;
                    a2[o] += g * e11;
                    a3[o] += g * e22;
                    a4[o] += g * e12;
                }
            }
        }
        #pragma unroll
        for (int o = 0; o < 13; o++) {
            float mu1 = a0[o], mu2 = a1[o];
            float m11 = mu1 * mu1, m22 = mu2 * mu2, m12 = mu1 * mu2;
            float s11 = a2[o] - m11;
            float s22 = a3[o] - m22;
            float s12 = a4[o] - m12;
            float v1 = 2.f * s12 + C2;
            float v2 = s11 + s22 + C2;
            float num = (2.f * m12 + C1) * v1;
            float den = (m11 + m22 + C1) * v2;
            lsum += __fdividef(num, den);
        }
    }
    __shared__ float sred[256];
    sred[threadIdx.x] = lsum;
    __syncthreads();
    #pragma unroll
    for (int off = 128; off; off >>= 1) {
        if (threadIdx.x < off) sred[threadIdx.x] += sred[threadIdx.x + off];
        __syncthreads();
    }
    if (threadIdx.x == 0) d_bsum[blockIdx.x] = sred[0];
}

// Deterministic final reduction over 3623 block sums.
__global__ void final_kernel(float* __restrict__ out) {
    __shared__ double sd[256];
    double s = 0.0;
    for (int i = threadIdx.x; i < 3623; i += 256) s += (double)d_bsum[i];
    sd[threadIdx.x] = s;
    __syncthreads();
    #pragma unroll
    for (int off = 128; off; off >>= 1) {
        if (threadIdx.x < off) sd[threadIdx.x] += sd[threadIdx.x + off];
        __syncthreads();
    }
    if (threadIdx.x == 0)
        out[0] = (float)(sd[0] / 12057136.0);   // 2 * 182^3
}

// ---------------------------------------------------------------------------

extern "C" void kernel_launch(void* const* d_in, const int* in_sizes, int n_in,
                              void* d_out, int out_size) {
    const float* img1 = (const float*)d_in[0];
    const float* img2 = (const float*)d_in[1];
    float* out = (float*)d_out;

    init_kernel<<<1, 1>>>();
    pass1_kernel<<<9216, 192>>>(img1, img2);   // 2*192*192 rows / 8
    const_kernel<<<1, 1>>>();
    pass2_kernel<<<4778, 256>>>();             // 5*2*192*7*91 threads (half2)
    pass3_kernel<<<3623, 256>>>();             // 2*14*182*182 threads
    final_kernel<<<1, 256>>>(out);
}